// round 6
// baseline (speedup 1.0000x reference)
#include <cuda_runtime.h>
#include <cstdint>

// FisherLayer: N=8192 rows, D=256 dims, K=32 components. Single fused kernel.
// out[0:K*D]     = mean_n gamma[n,k]*(y1^2-1)/sqrt(2)
// out[K*D:2*K*D] = mean_n gamma[n,k]*y1
// y1 = w*(x+b), gamma = softmax_k(-0.5*sum_d y1^2).
//
// Factored:
//   y4[n,k]   = -0.5*( sum_d w2*x^2 + sum_d (2*w2*b)*x + c_k ),  c_k = sum_d w2*b^2
//   S0[k], Sx[k,d] = sum_n gamma*x, Sx2[k,d] = sum_n gamma*x^2
//   out_mu    = w*(Sx + b*S0)/N
//   out_sigma = (w2*(Sx2 + 2*b*Sx + b^2*S0) - S0) / (sqrt(2)*N)
//
// One persistent kernel: 148 blocks x 512 threads (1 CTA/SM, co-resident),
// grid-wide spin barrier, then in-kernel reduction of L2-hot partials.

#define NROWS 8192
#define DD    256
#define KK    32
#define GRID_MAIN 148
#define NBATCH (NROWS / 8)   // 1024 batches of 8 rows
#define THREADS 512

typedef unsigned long long u64;

// scratch: g_P[chunk 0..127][row 0..147][32 float4]
//   col = p*256 + d (p = k-pair, d = dim); chunk = col>>5; within = col&31 = lane
//   float4 = (Sx[2p,d], Sx[2p+1,d], Sx2[2p,d], Sx2[2p+1,d])
__device__ __align__(128) float4 g_P[128 * GRID_MAIN * 32];
__device__ float    g_PS0[GRID_MAIN * KK];
__device__ unsigned g_ctr = 0;   // monotonic across graph replays

__device__ __forceinline__ u64 pack2(float lo, float hi) {
    u64 r; asm("mov.b64 %0, {%1, %2};" : "=l"(r) : "f"(lo), "f"(hi)); return r;
}
__device__ __forceinline__ float2 unpack2(u64 v) {
    float2 f; asm("mov.b64 {%0, %1}, %2;" : "=f"(f.x), "=f"(f.y) : "l"(v)); return f;
}
__device__ __forceinline__ u64 fma2(u64 a, u64 b, u64 c) {
    u64 d; asm("fma.rn.f32x2 %0, %1, %2, %3;" : "=l"(d) : "l"(a), "l"(b), "l"(c)); return d;
}

__global__ void __launch_bounds__(THREADS, 1) fisher_all(const float* __restrict__ x,
                                                         const float* __restrict__ w,
                                                         const float* __restrict__ b,
                                                         float* __restrict__ out) {
    __shared__ __align__(16) u64    s_xx2[8 * DD];      // (x^2, x) per [r*256 + d]  16KB
    __shared__ __align__(16) float  s_gamma[8 * KK];    // gamma [r][k]               1KB
    __shared__ float  s_part[16 * 256];                 // y4 partials [slice][r*32+k] 16KB
    __shared__ float  s_cred[16 * KK];                  // c / s0 reduce               2KB
    __shared__ __align__(16) float4 s_red4[16 * 32];    // fin reduce                  8KB
    __shared__ float  s_S0v[2];

    const int tid  = threadIdx.x;
    const int wrp  = tid >> 5;    // 0..15
    const int lane = tid & 31;
    const int bid  = blockIdx.x;

    // ---- params: warp owns d-slice [wrp*16, +16), lane = k ----
    u64 atu[16];
    float c_part = 0.0f;
    {
        const float* wr = w + lane * DD + wrp * 16;
        const float* br = b + lane * DD + wrp * 16;
        #pragma unroll
        for (int j = 0; j < 16; j++) {
            float wv = wr[j], bv = br[j];
            float w2 = wv * wv;
            atu[j] = pack2(w2, 2.0f * w2 * bv);
            c_part += w2 * bv * bv;
        }
    }
    s_cred[wrp * KK + lane] = c_part;

    // phase-B accumulators: thread owns (d = tid&255, khalf = tid>>8); k pairs
    u64 accx[8], accx2[8];
    #pragma unroll
    for (int m = 0; m < 8; m++) { accx[m] = 0ull; accx2[m] = 0ull; }
    float s0acc = 0.0f;

    int batch = bid;
    float xr[4];
    {
        const float* xb = x + (size_t)batch * 8 * DD;
        #pragma unroll
        for (int i = 0; i < 4; i++) xr[i] = xb[i * 512 + tid];
    }

    __syncthreads();
    float c_reg = 0.0f;
    #pragma unroll
    for (int j = 0; j < 16; j++) c_reg += s_cred[j * KK + lane];

    const int dphB = tid & 255;
    const int khB  = tid >> 8;

    for (;;) {
        // fill x buffer (x^2, x)
        #pragma unroll
        for (int i = 0; i < 4; i++) {
            float v = xr[i];
            s_xx2[i * 512 + tid] = pack2(v * v, v);
        }
        int nb = batch + GRID_MAIN;
        bool nh = nb < NBATCH;
        if (nh) {
            const float* xn = x + (size_t)nb * 8 * DD;
            #pragma unroll
            for (int i = 0; i < 4; i++) xr[i] = xn[i * 512 + tid];
        }
        __syncthreads();

        // ---- phase A: y4 partial over this warp's 16-wide d-slice ----
        {
            u64 accA[8];
            #pragma unroll
            for (int r = 0; r < 8; r++) accA[r] = 0ull;
            const int d0 = wrp * 16;
            #pragma unroll
            for (int j = 0; j < 16; j += 2) {
                #pragma unroll
                for (int r = 0; r < 8; r++) {
                    ulonglong2 v = *reinterpret_cast<const ulonglong2*>(&s_xx2[r * DD + d0 + j]);
                    accA[r] = fma2(atu[j],     v.x, accA[r]);
                    accA[r] = fma2(atu[j + 1], v.y, accA[r]);
                }
            }
            #pragma unroll
            for (int r = 0; r < 8; r++) {
                float2 p = unpack2(accA[r]);
                s_part[wrp * 256 + r * 32 + lane] = p.x + p.y;
            }
        }
        __syncthreads();

        // ---- softmax: warps 0..7, warp = row, lane = k ----
        if (wrp < 8) {
            float y = 0.0f;
            #pragma unroll
            for (int j = 0; j < 16; j++) y += s_part[j * 256 + wrp * 32 + lane];
            y = -0.5f * (y + c_reg);
            float m = y;
            #pragma unroll
            for (int o = 16; o; o >>= 1) m = fmaxf(m, __shfl_xor_sync(0xffffffffu, m, o));
            float e = __expf(y - m);
            float s = e;
            #pragma unroll
            for (int o = 16; o; o >>= 1) s += __shfl_xor_sync(0xffffffffu, s, o);
            float g = e / s;
            s0acc += g;
            s_gamma[wrp * KK + lane] = g;
        }
        __syncthreads();

        // ---- phase B: thread owns d, half the k's ----
        #pragma unroll
        for (int r = 0; r < 8; r++) {
            float2 xv = unpack2(s_xx2[r * DD + dphB]);   // (x^2, x)
            u64 pxx = pack2(xv.y, xv.y);
            u64 px2 = pack2(xv.x, xv.x);
            const ulonglong2* grow =
                reinterpret_cast<const ulonglong2*>(&s_gamma[r * KK + khB * 16]);
            #pragma unroll
            for (int q = 0; q < 4; q++) {
                ulonglong2 gg = grow[q];
                accx [2 * q]     = fma2(gg.x, pxx, accx [2 * q]);
                accx [2 * q + 1] = fma2(gg.y, pxx, accx [2 * q + 1]);
                accx2[2 * q]     = fma2(gg.x, px2, accx2[2 * q]);
                accx2[2 * q + 1] = fma2(gg.y, px2, accx2[2 * q + 1]);
            }
        }
        __syncthreads();   // protect s_xx2 / s_gamma before next batch

        if (!nh) break;
        batch = nb;
    }

    // ---- S0 per-block combine ----
    if (wrp < 8) s_cred[wrp * KK + lane] = s0acc;
    __syncthreads();
    if (wrp == 0) {
        float v = 0.0f;
        #pragma unroll
        for (int j = 0; j < 8; j++) v += s_cred[j * KK + lane];
        g_PS0[bid * KK + lane] = v;
    }

    // ---- write partials: chunk-major, coalesced STG.128 ----
    {
        ulonglong2* pg = reinterpret_cast<ulonglong2*>(g_P);
        const int dq = (tid >> 5) & 7;   // d>>5
        #pragma unroll
        for (int m = 0; m < 8; m++) {
            int p = khB * 8 + m;
            int chunk = p * 8 + dq;
            size_t idx = ((size_t)chunk * GRID_MAIN + bid) * 32 + lane;
            ulonglong2 v; v.x = accx[m]; v.y = accx2[m];
            pg[idx] = v;
        }
    }

    // ---- grid-wide barrier (all 148 CTAs co-resident: 1 CTA/SM) ----
    __threadfence();
    __syncthreads();
    if (tid == 0) {
        unsigned my = atomicAdd(&g_ctr, 1u);
        unsigned target = my - (my % (unsigned)GRID_MAIN) + (unsigned)GRID_MAIN;
        while (*(volatile unsigned*)&g_ctr < target) { }
    }
    __syncthreads();
    __threadfence();

    // ---- fused reduction + finalize: blocks 0..127 each own one chunk ----
    if (bid >= 128) return;
    const int cb = bid;
    const float4* src = g_P + (size_t)cb * GRID_MAIN * 32;
    const int q4 = tid & 31;
    const int rg = tid >> 5;       // 16 row-groups
    float4 a = make_float4(0.f, 0.f, 0.f, 0.f);
    #pragma unroll 2
    for (int r = rg; r < GRID_MAIN; r += 16) {
        float4 v = src[r * 32 + q4];
        a.x += v.x; a.y += v.y; a.z += v.z; a.w += v.w;
    }
    s_red4[rg * 32 + q4] = a;

    if (wrp == 1) {   // S0 for this chunk's two k's
        int ks = lane >> 4;        // 0/1
        int j  = lane & 15;
        int p  = cb >> 3;
        float s = 0.0f;
        for (int bb = j; bb < GRID_MAIN; bb += 16) s += g_PS0[bb * KK + 2 * p + ks];
        #pragma unroll
        for (int o = 1; o < 16; o <<= 1) s += __shfl_xor_sync(0xffffffffu, s, o);
        if (j == 0) s_S0v[ks] = s;
    }
    __syncthreads();

    if (tid < 32) {
        float4 tot = make_float4(0.f, 0.f, 0.f, 0.f);
        #pragma unroll
        for (int gq = 0; gq < 16; gq++) {
            float4 v = s_red4[gq * 32 + tid];
            tot.x += v.x; tot.y += v.y; tot.z += v.z; tot.w += v.w;
        }
        const int p  = cb >> 3;
        const int d  = (cb & 7) * 32 + tid;
        const int k0 = 2 * p, k1 = 2 * p + 1;
        const float invN   = 1.0f / (float)NROWS;
        const float invNs2 = invN * 0.70710678118654752440f;

        {
            float wv = w[k0 * DD + d], bv = b[k0 * DD + d], S0 = s_S0v[0];
            float mu  = wv * (tot.x + bv * S0) * invN;
            float Ey2 = wv * wv * (tot.z + 2.0f * bv * tot.x + bv * bv * S0);
            out[k0 * DD + d]           = (Ey2 - S0) * invNs2;
            out[KK * DD + k0 * DD + d] = mu;
        }
        {
            float wv = w[k1 * DD + d], bv = b[k1 * DD + d], S0 = s_S0v[1];
            float mu  = wv * (tot.y + bv * S0) * invN;
            float Ey2 = wv * wv * (tot.w + 2.0f * bv * tot.y + bv * bv * S0);
            out[k1 * DD + d]           = (Ey2 - S0) * invNs2;
            out[KK * DD + k1 * DD + d] = mu;
        }
    }
}

extern "C" void kernel_launch(void* const* d_in, const int* in_sizes, int n_in,
                              void* d_out, int out_size) {
    const float* x = (const float*)d_in[0];
    const float* w = (const float*)d_in[1];
    const float* b = (const float*)d_in[2];
    float* out = (float*)d_out;
    (void)in_sizes; (void)n_in; (void)out_size;

    fisher_all<<<GRID_MAIN, THREADS>>>(x, w, b, out);
}

// round 7
// speedup vs baseline: 1.0095x; 1.0095x over previous
#include <cuda_runtime.h>
#include <cstdint>

// FisherLayer: N=8192 rows, D=256 dims, K=32 components. Single fused kernel:
// R5-proven compute loop (256 thr, double-buffered) + in-kernel grid barrier
// + L2-hot reduction (no second kernel, no atomics on data).
//
// Factored:
//   y4[n,k]   = -0.5*( sum_d w2*x^2 + sum_d (2*w2*b)*x + c_k ),  c_k = sum_d w2*b^2
//   S0[k], Sx[k,d] = sum_n gamma*x, Sx2[k,d] = sum_n gamma*x^2
//   out_mu    = w*(Sx + b*S0)/N
//   out_sigma = (w2*(Sx2 + 2*b*Sx + b^2*S0) - S0) / (sqrt(2)*N)

#define NROWS 8192
#define DD    256
#define KK    32
#define GRID_MAIN 148
#define NBATCH (NROWS / 8)   // 1024 batches of 8 rows
#define THREADS 256

typedef unsigned long long u64;

// scratch: g_P[chunk 0..127][row 0..147][32 float4]
//   col = p*256 + d; chunk = col>>5; within-chunk = d&31
//   float4 = (Sx[2p,d], Sx[2p+1,d], Sx2[2p,d], Sx2[2p+1,d])
__device__ __align__(128) float4 g_P[128 * GRID_MAIN * 32];
__device__ float    g_PS0[GRID_MAIN * KK];
__device__ unsigned g_ctr = 0;   // monotonic across graph replays

__device__ __forceinline__ u64 pack2(float lo, float hi) {
    u64 r; asm("mov.b64 %0, {%1, %2};" : "=l"(r) : "f"(lo), "f"(hi)); return r;
}
__device__ __forceinline__ float2 unpack2(u64 v) {
    float2 f; asm("mov.b64 {%0, %1}, %2;" : "=f"(f.x), "=f"(f.y) : "l"(v)); return f;
}
__device__ __forceinline__ u64 fma2(u64 a, u64 b, u64 c) {
    u64 d; asm("fma.rn.f32x2 %0, %1, %2, %3;" : "=l"(d) : "l"(a), "l"(b), "l"(c)); return d;
}

__global__ void __launch_bounds__(THREADS, 1) fisher_all(const float* __restrict__ x,
                                                         const float* __restrict__ w,
                                                         const float* __restrict__ b,
                                                         float* __restrict__ out) {
    __shared__ __align__(16) u64   s_xx2[2][8 * DD];   // (x^2, x) per [r*D + d]  32KB
    __shared__ __align__(16) float s_gamma[8 * KK];    // gamma [r][k]             1KB
    __shared__ __align__(16) float s_part[8 * 256];    // y4 partials / reduce     8KB
    __shared__ float s_cred[8 * KK];                   // c / s0 reduce            1KB
    __shared__ float s_S0v[2];

    const int tid  = threadIdx.x;
    const int wrp  = tid >> 5;   // 0..7
    const int lane = tid & 31;
    const int bid  = blockIdx.x;

    // ---- params: warp owns d-slice [wrp*32, +32), lane = k ----
    u64 atu[32];
    float c_part = 0.0f;
    {
        const float* wr = w + lane * DD + wrp * 32;
        const float* br = b + lane * DD + wrp * 32;
        #pragma unroll
        for (int j = 0; j < 32; j++) {
            float wv = wr[j], bv = br[j];
            float w2 = wv * wv;
            atu[j] = pack2(w2, 2.0f * w2 * bv);
            c_part += w2 * bv * bv;
        }
    }
    s_cred[wrp * KK + lane] = c_part;

    // phase-B accumulators: thread owns d=tid; pair-packed over k
    u64 accx[16], accx2[16];
    #pragma unroll
    for (int p = 0; p < 16; p++) { accx[p] = 0ull; accx2[p] = 0ull; }
    float s0acc = 0.0f;

    int batch = bid;
    bool have = true;

    float xr[8];
    {
        const float* xb = x + (size_t)batch * 8 * DD;
        #pragma unroll
        for (int r = 0; r < 8; r++) xr[r] = xb[r * DD + tid];
    }

    __syncthreads();
    float c_reg = 0.0f;
    #pragma unroll
    for (int j = 0; j < 8; j++) c_reg += s_cred[j * KK + lane];

    int bufsel = 0;
    while (have) {
        u64* buf = s_xx2[bufsel];
        float cx[8];
        #pragma unroll
        for (int r = 0; r < 8; r++) {
            cx[r] = xr[r];
            buf[r * DD + tid] = pack2(cx[r] * cx[r], cx[r]);
        }

        int nbatch = batch + GRID_MAIN;
        bool nhave = nbatch < NBATCH;
        if (nhave) {
            const float* xb = x + (size_t)nbatch * 8 * DD;
            #pragma unroll
            for (int r = 0; r < 8; r++) xr[r] = xb[r * DD + tid];
        }
        __syncthreads();

        // ---- phase A: y4 partial over this warp's 32-wide d-slice ----
        {
            u64 accA[8];
            #pragma unroll
            for (int r = 0; r < 8; r++) accA[r] = 0ull;
            #pragma unroll
            for (int j = 0; j < 32; j += 2) {
                const int d0 = wrp * 32 + j;
                #pragma unroll
                for (int r = 0; r < 8; r++) {
                    ulonglong2 v = *reinterpret_cast<const ulonglong2*>(&buf[r * DD + d0]);
                    accA[r] = fma2(atu[j],     v.x, accA[r]);
                    accA[r] = fma2(atu[j + 1], v.y, accA[r]);
                }
            }
            #pragma unroll
            for (int r = 0; r < 8; r++) {
                float2 p = unpack2(accA[r]);
                s_part[wrp * 256 + r * 32 + lane] = p.x + p.y;
            }
        }
        __syncthreads();

        // ---- softmax: warp wrp owns row r=wrp, lane = k ----
        {
            float y = 0.0f;
            #pragma unroll
            for (int j = 0; j < 8; j++) y += s_part[j * 256 + wrp * 32 + lane];
            y = -0.5f * (y + c_reg);
            float m = y;
            #pragma unroll
            for (int o = 16; o; o >>= 1) m = fmaxf(m, __shfl_xor_sync(0xffffffffu, m, o));
            float e = __expf(y - m);
            float s = e;
            #pragma unroll
            for (int o = 16; o; o >>= 1) s += __shfl_xor_sync(0xffffffffu, s, o);
            float g = e / s;
            s0acc += g;
            s_gamma[wrp * KK + lane] = g;
        }
        __syncthreads();

        // ---- phase B: thread owns d=tid; gamma as packed float pairs ----
        #pragma unroll
        for (int r = 0; r < 8; r++) {
            float xv = cx[r];
            u64 pxx = pack2(xv, xv);
            float x2 = xv * xv;
            u64 px2 = pack2(x2, x2);
            const ulonglong2* grow = reinterpret_cast<const ulonglong2*>(&s_gamma[r * KK]);
            #pragma unroll
            for (int q = 0; q < 8; q++) {
                ulonglong2 gg = grow[q];
                accx [2 * q]     = fma2(gg.x, pxx, accx [2 * q]);
                accx [2 * q + 1] = fma2(gg.y, pxx, accx [2 * q + 1]);
                accx2[2 * q]     = fma2(gg.x, px2, accx2[2 * q]);
                accx2[2 * q + 1] = fma2(gg.y, px2, accx2[2 * q + 1]);
            }
        }

        batch = nbatch;
        have = nhave;
        bufsel ^= 1;
    }

    // ---- S0 per-block combine ----
    __syncthreads();
    s_cred[wrp * KK + lane] = s0acc;
    __syncthreads();
    if (wrp == 0) {
        float v = 0.0f;
        #pragma unroll
        for (int j = 0; j < 8; j++) v += s_cred[j * KK + lane];
        g_PS0[bid * KK + lane] = v;
    }

    // ---- write partials: chunk-major, coalesced STG.128 ----
    {
        ulonglong2* pg = reinterpret_cast<ulonglong2*>(g_P);
        #pragma unroll
        for (int p = 0; p < 16; p++) {
            int chunk = p * 8 + wrp;                       // (d>>5) = wrp
            size_t idx = ((size_t)chunk * GRID_MAIN + bid) * 32 + lane;
            ulonglong2 v; v.x = accx[p]; v.y = accx2[p];
            pg[idx] = v;
        }
    }

    // ---- grid-wide barrier (148 CTAs, 1/SM, co-resident) ----
    __threadfence();
    __syncthreads();
    if (bid >= 128) {
        if (tid == 0) atomicAdd(&g_ctr, 1u);   // arrive only, then exit
        return;
    }
    if (tid == 0) {
        unsigned my = atomicAdd(&g_ctr, 1u);
        unsigned target = my - (my % (unsigned)GRID_MAIN) + (unsigned)GRID_MAIN;
        while (*(volatile unsigned*)&g_ctr < target) { }
    }
    __syncthreads();
    __threadfence();

    // ---- fused reduction + finalize: blocks 0..127 each own one chunk ----
    const int cb = bid;
    const float4* src = g_P + (size_t)cb * GRID_MAIN * 32;
    float4* s_red4 = reinterpret_cast<float4*>(s_part);   // reuse 8KB
    const int q4 = tid & 31;
    const int rg = tid >> 5;       // 8 row-groups
    float4 a = make_float4(0.f, 0.f, 0.f, 0.f);
    #pragma unroll 2
    for (int r = rg; r < GRID_MAIN; r += 8) {
        float4 v = src[r * 32 + q4];
        a.x += v.x; a.y += v.y; a.z += v.z; a.w += v.w;
    }
    s_red4[rg * 32 + q4] = a;

    if (wrp == 1) {   // S0 for this chunk's two k's
        int ks = lane >> 4;        // 0/1
        int j  = lane & 15;
        int p  = cb >> 3;
        float s = 0.0f;
        for (int bb = j; bb < GRID_MAIN; bb += 16) s += g_PS0[bb * KK + 2 * p + ks];
        #pragma unroll
        for (int o = 1; o < 16; o <<= 1) s += __shfl_xor_sync(0xffffffffu, s, o);
        if (j == 0) s_S0v[ks] = s;
    }
    __syncthreads();

    if (tid < 32) {
        float4 tot = make_float4(0.f, 0.f, 0.f, 0.f);
        #pragma unroll
        for (int gq = 0; gq < 8; gq++) {
            float4 v = s_red4[gq * 32 + tid];
            tot.x += v.x; tot.y += v.y; tot.z += v.z; tot.w += v.w;
        }
        const int p  = cb >> 3;
        const int d  = (cb & 7) * 32 + tid;
        const int k0 = 2 * p, k1 = 2 * p + 1;
        const float invN   = 1.0f / (float)NROWS;
        const float invNs2 = invN * 0.70710678118654752440f;

        {
            float wv = w[k0 * DD + d], bv = b[k0 * DD + d], S0 = s_S0v[0];
            float mu  = wv * (tot.x + bv * S0) * invN;
            float Ey2 = wv * wv * (tot.z + 2.0f * bv * tot.x + bv * bv * S0);
            out[k0 * DD + d]           = (Ey2 - S0) * invNs2;
            out[KK * DD + k0 * DD + d] = mu;
        }
        {
            float wv = w[k1 * DD + d], bv = b[k1 * DD + d], S0 = s_S0v[1];
            float mu  = wv * (tot.y + bv * S0) * invN;
            float Ey2 = wv * wv * (tot.w + 2.0f * bv * tot.y + bv * bv * S0);
            out[k1 * DD + d]           = (Ey2 - S0) * invNs2;
            out[KK * DD + k1 * DD + d] = mu;
        }
    }
}

extern "C" void kernel_launch(void* const* d_in, const int* in_sizes, int n_in,
                              void* d_out, int out_size) {
    const float* x = (const float*)d_in[0];
    const float* w = (const float*)d_in[1];
    const float* b = (const float*)d_in[2];
    float* out = (float*)d_out;
    (void)in_sizes; (void)n_in; (void)out_size;

    fisher_all<<<GRID_MAIN, THREADS>>>(x, w, b, out);
}

// round 8
// speedup vs baseline: 1.0571x; 1.0471x over previous
#include <cuda_runtime.h>
#include <cstdint>

// FisherLayer: N=8192, D=256, K=32. Single fused persistent kernel.
//   y4[n,k]   = -0.5*( sum_d a*x^2 + sum_d u*x + c_k ),  a=w^2, u=2w^2 b, c_k=sum a b^2
//               with per-element factoring: a*x^2 + u*x = x*(a*x + u)
//   S0[k], Sx[k,d]=sum_n g*x, Sx2[k,d]=sum_n g*x^2
//   out_mu    = w*(Sx + b*S0)/N
//   out_sigma = (w^2*(Sx2 + 2*b*Sx + b^2*S0) - S0)/(sqrt(2)*N)
// LDS-minimized: raw-x tile (LDS.128 = 4 dims), phase-B k-half split.

#define NROWS 8192
#define DD    256
#define KK    32
#define GRID_MAIN 148
#define NBATCH (NROWS / 8)
#define THREADS 256

typedef unsigned long long u64;

// g_P[chunk 0..127][row 0..147][32 float4]; col = p*256+d; chunk=col>>5
// float4 = (Sx[2p,d], Sx[2p+1,d], Sx2[2p,d], Sx2[2p+1,d])
__device__ __align__(128) float4 g_P[128 * GRID_MAIN * 32];
__device__ float    g_PS0[GRID_MAIN * KK];
__device__ unsigned g_ctr = 0;   // monotonic across graph replays

__device__ __forceinline__ u64 pack2(float lo, float hi) {
    u64 r; asm("mov.b64 %0, {%1, %2};" : "=l"(r) : "f"(lo), "f"(hi)); return r;
}
__device__ __forceinline__ float2 unpack2(u64 v) {
    float2 f; asm("mov.b64 {%0, %1}, %2;" : "=f"(f.x), "=f"(f.y) : "l"(v)); return f;
}
__device__ __forceinline__ u64 fma2(u64 a, u64 b, u64 c) {
    u64 d; asm("fma.rn.f32x2 %0, %1, %2, %3;" : "=l"(d) : "l"(a), "l"(b), "l"(c)); return d;
}

__global__ void __launch_bounds__(THREADS, 1) fisher_all(const float* __restrict__ x,
                                                         const float* __restrict__ w,
                                                         const float* __restrict__ b,
                                                         float* __restrict__ out) {
    __shared__ __align__(16) float4 s_x4[2][512];      // raw x, 8 rows x 256   16KB
    __shared__ __align__(16) float  s_gamma[8 * KK];   // gamma [r][k]           1KB
    __shared__ __align__(16) float  s_part[8 * 256];   // y4 partials / reduce   8KB
    __shared__ float s_cred[8 * KK];
    __shared__ float s_S0v[2];

    const int tid  = threadIdx.x;
    const int wrp  = tid >> 5;   // 0..7
    const int lane = tid & 31;
    const int bid  = blockIdx.x;

    // ---- params: warp owns d-slice [wrp*32,+32), lane = k; pairs over d ----
    u64 ap[16], up[16];
    float c_part = 0.0f;
    {
        const float* wr = w + lane * DD + wrp * 32;
        const float* br = b + lane * DD + wrp * 32;
        #pragma unroll
        for (int j = 0; j < 16; j++) {
            float w0 = wr[2 * j], w1 = wr[2 * j + 1];
            float b0 = br[2 * j], b1 = br[2 * j + 1];
            float a0 = w0 * w0, a1 = w1 * w1;
            ap[j] = pack2(a0, a1);
            up[j] = pack2(2.0f * a0 * b0, 2.0f * a1 * b1);
            c_part += a0 * b0 * b0 + a1 * b1 * b1;
        }
    }
    s_cred[wrp * KK + lane] = c_part;

    // phase-B: thread owns d-pair dp = tid&127 (d = 2dp, 2dp+1), k-half kh = tid>>7
    const int dp = tid & 127;
    const int kh = tid >> 7;
    u64 accx0[8], accx1[8], accx20[8], accx21[8];   // [k-pair p] for d0 / d1
    #pragma unroll
    for (int p = 0; p < 8; p++) { accx0[p] = 0; accx1[p] = 0; accx20[p] = 0; accx21[p] = 0; }
    float s0acc = 0.0f;

    int batch = bid;
    float4 v0, v1;
    {
        const float4* xb = reinterpret_cast<const float4*>(x) + (size_t)batch * 512;
        v0 = xb[tid]; v1 = xb[tid + 256];
    }

    __syncthreads();
    float c_reg = 0.0f;
    #pragma unroll
    for (int j = 0; j < 8; j++) c_reg += s_cred[j * KK + lane];

    int bufsel = 0;
    for (;;) {
        s_x4[bufsel][tid] = v0;
        s_x4[bufsel][tid + 256] = v1;

        int nbatch = batch + GRID_MAIN;
        bool nhave = nbatch < NBATCH;
        if (nhave) {
            const float4* xb = reinterpret_cast<const float4*>(x) + (size_t)nbatch * 512;
            v0 = xb[tid]; v1 = xb[tid + 256];
        }
        __syncthreads();

        const ulonglong2* bx = reinterpret_cast<const ulonglong2*>(s_x4[bufsel]);

        // ---- phase A: acc_r += x*(a*x+u) over warp's 32-wide d-slice ----
        {
            u64 accA[8];
            #pragma unroll
            for (int r = 0; r < 8; r++) accA[r] = 0ull;
            #pragma unroll
            for (int q = 0; q < 8; q++) {
                #pragma unroll
                for (int r = 0; r < 8; r++) {
                    ulonglong2 v = bx[r * 64 + wrp * 8 + q];
                    u64 t0 = fma2(ap[2 * q],     v.x, up[2 * q]);
                    accA[r] = fma2(v.x, t0, accA[r]);
                    u64 t1 = fma2(ap[2 * q + 1], v.y, up[2 * q + 1]);
                    accA[r] = fma2(v.y, t1, accA[r]);
                }
            }
            #pragma unroll
            for (int r = 0; r < 8; r++) {
                float2 p = unpack2(accA[r]);
                s_part[wrp * 256 + r * 32 + lane] = p.x + p.y;
            }
        }
        __syncthreads();

        // ---- softmax: warp wrp owns row r=wrp, lane = k ----
        {
            float y = 0.0f;
            #pragma unroll
            for (int j = 0; j < 8; j++) y += s_part[j * 256 + wrp * 32 + lane];
            y = -0.5f * (y + c_reg);
            float m = y;
            #pragma unroll
            for (int o = 16; o; o >>= 1) m = fmaxf(m, __shfl_xor_sync(0xffffffffu, m, o));
            float e = __expf(y - m);
            float s = e;
            #pragma unroll
            for (int o = 16; o; o >>= 1) s += __shfl_xor_sync(0xffffffffu, s, o);
            float g = e / s;
            s0acc += g;
            s_gamma[wrp * KK + lane] = g;
        }
        __syncthreads();

        // ---- phase B: (Sx, Sx2) for 2 d's x 16 k's ----
        {
            const float2* xf2 = reinterpret_cast<const float2*>(s_x4[bufsel]);
            #pragma unroll
            for (int r = 0; r < 8; r++) {
                float2 xv = xf2[r * 128 + dp];
                float sq0 = xv.x * xv.x, sq1 = xv.y * xv.y;
                u64 p0  = pack2(xv.x, xv.x), p1  = pack2(xv.y, xv.y);
                u64 p0s = pack2(sq0, sq0),   p1s = pack2(sq1, sq1);
                const ulonglong2* grow =
                    reinterpret_cast<const ulonglong2*>(&s_gamma[r * KK + kh * 16]);
                #pragma unroll
                for (int t = 0; t < 4; t++) {
                    ulonglong2 gg = grow[t];   // (g2p,g2p+1) for p=2t, 2t+1
                    accx0 [2 * t]     = fma2(gg.x, p0,  accx0 [2 * t]);
                    accx1 [2 * t]     = fma2(gg.x, p1,  accx1 [2 * t]);
                    accx20[2 * t]     = fma2(gg.x, p0s, accx20[2 * t]);
                    accx21[2 * t]     = fma2(gg.x, p1s, accx21[2 * t]);
                    accx0 [2 * t + 1] = fma2(gg.y, p0,  accx0 [2 * t + 1]);
                    accx1 [2 * t + 1] = fma2(gg.y, p1,  accx1 [2 * t + 1]);
                    accx20[2 * t + 1] = fma2(gg.y, p0s, accx20[2 * t + 1]);
                    accx21[2 * t + 1] = fma2(gg.y, p1s, accx21[2 * t + 1]);
                }
            }
        }

        if (!nhave) break;
        batch = nbatch;
        bufsel ^= 1;
    }

    // ---- S0 per-block combine ----
    __syncthreads();
    s_cred[wrp * KK + lane] = s0acc;
    __syncthreads();
    if (wrp == 0) {
        float v = 0.0f;
        #pragma unroll
        for (int j = 0; j < 8; j++) v += s_cred[j * KK + lane];
        g_PS0[bid * KK + lane] = v;
    }

    // ---- write partials: (dp,kh,di,p) -> chunk-major g_P ----
    {
        ulonglong2* pg = reinterpret_cast<ulonglong2*>(g_P);
        const int d0 = 2 * dp;
        #pragma unroll
        for (int p = 0; p < 8; p++) {
            int pg_idx = kh * 8 + p;
            {   // di = 0
                int d = d0;
                int chunk = pg_idx * 8 + (d >> 5);
                size_t idx = ((size_t)chunk * GRID_MAIN + bid) * 32 + (d & 31);
                ulonglong2 v; v.x = accx0[p]; v.y = accx20[p];
                pg[idx] = v;
            }
            {   // di = 1
                int d = d0 + 1;
                int chunk = pg_idx * 8 + (d >> 5);
                size_t idx = ((size_t)chunk * GRID_MAIN + bid) * 32 + (d & 31);
                ulonglong2 v; v.x = accx1[p]; v.y = accx21[p];
                pg[idx] = v;
            }
        }
    }

    // ---- grid-wide barrier (148 CTAs, 1/SM) ----
    __threadfence();
    __syncthreads();
    if (bid >= 128) {
        if (tid == 0) atomicAdd(&g_ctr, 1u);
        return;
    }
    if (tid == 0) {
        unsigned my = atomicAdd(&g_ctr, 1u);
        unsigned target = my - (my % (unsigned)GRID_MAIN) + (unsigned)GRID_MAIN;
        while (*(volatile unsigned*)&g_ctr < target) { }
    }
    __syncthreads();
    __threadfence();

    // ---- fused reduction + finalize: blocks 0..127, one chunk each ----
    const int cb = bid;
    const float4* src = g_P + (size_t)cb * GRID_MAIN * 32;
    float4* s_red4 = reinterpret_cast<float4*>(s_part);
    const int q4 = tid & 31;
    const int rg = tid >> 5;
    float4 a = make_float4(0.f, 0.f, 0.f, 0.f);
    #pragma unroll 2
    for (int r = rg; r < GRID_MAIN; r += 8) {
        float4 v = src[r * 32 + q4];
        a.x += v.x; a.y += v.y; a.z += v.z; a.w += v.w;
    }
    s_red4[rg * 32 + q4] = a;

    if (wrp == 1) {   // S0 for this chunk's two k's
        int ks = lane >> 4;
        int j  = lane & 15;
        int p  = cb >> 3;
        float s = 0.0f;
        for (int bb = j; bb < GRID_MAIN; bb += 16) s += g_PS0[bb * KK + 2 * p + ks];
        #pragma unroll
        for (int o = 1; o < 16; o <<= 1) s += __shfl_xor_sync(0xffffffffu, s, o);
        if (j == 0) s_S0v[ks] = s;
    }
    __syncthreads();

    if (tid < 32) {
        float4 tot = make_float4(0.f, 0.f, 0.f, 0.f);
        #pragma unroll
        for (int gq = 0; gq < 8; gq++) {
            float4 v = s_red4[gq * 32 + tid];
            tot.x += v.x; tot.y += v.y; tot.z += v.z; tot.w += v.w;
        }
        const int p  = cb >> 3;
        const int d  = (cb & 7) * 32 + tid;
        const int k0 = 2 * p, k1 = 2 * p + 1;
        const float invN   = 1.0f / (float)NROWS;
        const float invNs2 = invN * 0.70710678118654752440f;

        {
            float wv = w[k0 * DD + d], bv = b[k0 * DD + d], S0 = s_S0v[0];
            float mu  = wv * (tot.x + bv * S0) * invN;
            float Ey2 = wv * wv * (tot.z + 2.0f * bv * tot.x + bv * bv * S0);
            out[k0 * DD + d]           = (Ey2 - S0) * invNs2;
            out[KK * DD + k0 * DD + d] = mu;
        }
        {
            float wv = w[k1 * DD + d], bv = b[k1 * DD + d], S0 = s_S0v[1];
            float mu  = wv * (tot.y + bv * S0) * invN;
            float Ey2 = wv * wv * (tot.w + 2.0f * bv * tot.y + bv * bv * S0);
            out[k1 * DD + d]           = (Ey2 - S0) * invNs2;
            out[KK * DD + k1 * DD + d] = mu;
        }
    }
}

extern "C" void kernel_launch(void* const* d_in, const int* in_sizes, int n_in,
                              void* d_out, int out_size) {
    const float* x = (const float*)d_in[0];
    const float* w = (const float*)d_in[1];
    const float* b = (const float*)d_in[2];
    float* out = (float*)d_out;
    (void)in_sizes; (void)n_in; (void)out_size;

    fisher_all<<<GRID_MAIN, THREADS>>>(x, w, b, out);
}